// round 15
// baseline (speedup 1.0000x reference)
#include <cuda_runtime.h>
#include <cstdint>

#define LQ    256
#define DIM   256
#define CH    32
#define BATCH 8
#define XSTR  260   // x-tile row stride (floats): bank = 4*tg+tq => conflict-free

// -------- scratch (device globals; no cudaMalloc allowed) -------------------
__device__ float    g_h[(size_t)BATCH * LQ * LQ * CH];       // 64 MB hidden
__device__ float    g_q[(size_t)BATCH * 7 * LQ * LQ];        // 14.7 MB row-conv
__device__ uint32_t g_wf[16384];                             // W1 tf32 B-fragments
__device__ int      g_ctr;                                   // persistent work counter

#define NKEEP  144                        // upper-triangle 8x32 blocks per batch
#define NTILE  (NKEEP * BATCH)            // 1152 total tiles
#define NPERS  444                        // persistent CTAs (148 SM x 3)

// -------- f32x2 helpers ------------------------------------------------------
__device__ __forceinline__ unsigned long long pk2(float lo, float hi) {
    unsigned long long r;
    asm("mov.b64 %0, {%1, %2};" : "=l"(r) : "f"(lo), "f"(hi));
    return r;
}
__device__ __forceinline__ void fma2(unsigned long long& a,
                                     unsigned long long x, unsigned long long y) {
    asm("fma.rn.f32x2 %0, %1, %2, %0;" : "+l"(a) : "l"(x), "l"(y));
}
__device__ __forceinline__ float2 up2(unsigned long long v) {
    float lo, hi;
    asm("mov.b64 {%0, %1}, %2;" : "=f"(lo), "=f"(hi) : "l"(v));
    return make_float2(lo, hi);
}

// -------- tf32 mma helpers ---------------------------------------------------
__device__ __forceinline__ uint32_t tf32c(float v) {     // round-to-nearest tf32
    uint32_t u;
    asm("cvt.rna.tf32.f32 %0, %1;" : "=r"(u) : "f"(v));
    return u;
}
__device__ __forceinline__ void mma_tf32(float* d, const uint32_t* a, const uint32_t* b) {
    asm volatile(
        "mma.sync.aligned.m16n8k8.row.col.f32.tf32.tf32.f32 "
        "{%0,%1,%2,%3}, {%4,%5,%6,%7}, {%8,%9}, {%0,%1,%2,%3};"
        : "+f"(d[0]), "+f"(d[1]), "+f"(d[2]), "+f"(d[3])
        : "r"(a[0]), "r"(a[1]), "r"(a[2]), "r"(a[3]), "r"(b[0]), "r"(b[1]));
}

// ---- Kernel 0: precompute W1 tf32 fragments + reset work counter ------------
__global__ __launch_bounds__(256) void k_prewf(const float* __restrict__ W1) {
    if (blockIdx.x == 0 && threadIdx.x == 0) g_ctr = 0;
    int idx = blockIdx.x * 256 + threadIdx.x;       // [0, 16384)
    int e = idx & 1, t = (idx >> 1) & 31, f = (idx >> 6) & 3;
    int h = (idx >> 8) & 1, kb = idx >> 9;
    int k = (t & 3) + 4 * e, n = f * 8 + (t >> 2);
    int d = h * 256 + kb * 8 + k;
    g_wf[idx] = tf32c(W1[d * 32 + n]);
}

// smem layout for k_pair (byte offsets)
#define S_B1   0
#define S_TILE 128
#define S_XI   256
#define S_XJ   (S_XI + 8 * XSTR * 4)      // 8576
#define SMEM1  (S_XJ + 32 * XSTR * 4)     // 41856
// per SM: 3 x 41856 = 125568 B < 228 KB; regs 77 x 768 thr = 59136 < 65536

// ---- Kernel 1: persistent symmetric pairwise-feature GEMM (mma.sync tf32) ---
// h[b,i,j,:] == h[b,j,i,:] exactly. Tiles pulled from a global atomic counter;
// fully-masked tiles cost only zero-stores.
__global__ __launch_bounds__(256, 3)
void k_pair(const float* __restrict__ X, const int* __restrict__ plen_p,
            const float* __restrict__ b1) {
    extern __shared__ char smem[];
    float* sB1  = (float*)(smem + S_B1);
    int*   sTl  = (int*)(smem + S_TILE);
    float* sXi  = (float*)(smem + S_XI);
    float* sXj  = (float*)(smem + S_XJ);

    const int tid = threadIdx.x;
    const int w    = tid >> 5;
    const int lane = tid & 31;
    const int tg = lane >> 2, tq = lane & 3;

    if (tid < 32) sB1[tid] = b1[tid];

    for (;;) {
        if (tid == 0) sTl[0] = atomicAdd(&g_ctr, 1);
        __syncthreads();                           // publishes sTl, guards smem reuse
        const int tile = sTl[0];
        if (tile >= NTILE) break;

        const int b   = tile / NKEEP;
        const int idx = tile - b * NKEEP;
        // kept-block index -> (ib, jb): count up to jb is 2*jb^2+2*jb.
        int jb = (int)floorf((sqrtf((float)(4 * idx) + 9.0f) - 3.0f) * 0.5f);
        while (2 * (jb + 1) * (jb + 1) + 2 * (jb + 1) <= idx) ++jb;
        while (2 * jb * jb + 2 * jb > idx) --jb;
        const int ib = idx - (2 * jb * jb + 2 * jb);
        const int i0 = ib * 8, j0 = jb * 32;
        const float* Xb = X + (size_t)b * LQ * DIM;
        const int plen = __ldg(plen_p + b);
        const bool live = (i0 < plen) && (j0 < plen);

        float acc[2][4][4];
        #pragma unroll
        for (int a = 0; a < 2; ++a)
            #pragma unroll
            for (int f = 0; f < 4; ++f)
                #pragma unroll
                for (int e = 0; e < 4; ++e) acc[a][f][e] = 0.f;

        if (live) {
            for (int t = tid; t < 8 * 64; t += 256) {
                int r = t >> 6, q = t & 63;
                *(float4*)(sXi + r * XSTR + q * 4) =
                    ((const float4*)(Xb + (size_t)(i0 + r) * DIM))[q];
            }
            for (int t = tid; t < 32 * 64; t += 256) {
                int r = t >> 6, q = t & 63;
                *(float4*)(sXj + r * XSTR + q * 4) =
                    ((const float4*)(Xb + (size_t)(j0 + r) * DIM))[q];
            }
            __syncthreads();

            const float* xiw = sXi + w * XSTR;
            const float2* wfb = (const float2*)g_wf + lane;

            #pragma unroll 2
            for (int kb = 0; kb < 32; ++kb) {
                const int d0 = kb * 8;
                const float2* wf = wfb + (size_t)kb * 256;
                uint32_t Bm[4][2], Bs[4][2];
                #pragma unroll
                for (int f = 0; f < 4; ++f) {
                    float2 v0 = __ldg(wf + f * 32);
                    float2 v1 = __ldg(wf + 128 + f * 32);
                    Bm[f][0] = __float_as_uint(v0.x); Bm[f][1] = __float_as_uint(v0.y);
                    Bs[f][0] = __float_as_uint(v1.x); Bs[f][1] = __float_as_uint(v1.y);
                }
                const float xi0 = xiw[d0 + tq];
                const float xi1 = xiw[d0 + tq + 4];
                float xa[4], xb_[4];
                #pragma unroll
                for (int a = 0; a < 4; ++a) {
                    const float* xr = sXj + (tg + a * 8) * XSTR + d0;
                    xa[a] = xr[tq]; xb_[a] = xr[tq + 4];
                }
                uint32_t Am[2][4], As[2][4];
                #pragma unroll
                for (int fr = 0; fr < 2; ++fr) {
                    const int r0 = fr * 2, r1 = fr * 2 + 1;
                    Am[fr][0] = tf32c(xi0 * xa[r0]);
                    Am[fr][1] = tf32c(xi0 * xa[r1]);
                    Am[fr][2] = tf32c(xi1 * xb_[r0]);
                    Am[fr][3] = tf32c(xi1 * xb_[r1]);
                    As[fr][0] = tf32c(fabsf(xi0 - xa[r0]));
                    As[fr][1] = tf32c(fabsf(xi0 - xa[r1]));
                    As[fr][2] = tf32c(fabsf(xi1 - xb_[r0]));
                    As[fr][3] = tf32c(fabsf(xi1 - xb_[r1]));
                }
                #pragma unroll
                for (int fr = 0; fr < 2; ++fr)
                    #pragma unroll
                    for (int f = 0; f < 4; ++f) {
                        mma_tf32(acc[fr][f], Am[fr], Bm[f]);
                        mma_tf32(acc[fr][f], As[fr], Bs[f]);
                    }
            }
        }

        // epilogue: bias+relu+mask -> g_h[b][i][j][:] AND mirror g_h[b][j][i][:]
        const int gi = i0 + w;
        const bool vi = gi < plen;
        #pragma unroll
        for (int fr = 0; fr < 2; ++fr) {
            #pragma unroll
            for (int s = 0; s < 2; ++s) {
                const int gj = j0 + fr * 16 + tg + 8 * s;
                const bool v = vi && (gj < plen);
                float* Hrow = g_h + ((size_t)(b * LQ + gi) * LQ + gj) * CH;
                float* Hcol = g_h + ((size_t)(b * LQ + gj) * LQ + gi) * CH;
                #pragma unroll
                for (int f = 0; f < 4; ++f) {
                    const int ch = f * 8 + 2 * tq;
                    float2 val;
                    val.x = v ? fmaxf(acc[fr][f][2 * s]     + sB1[ch],     0.f) : 0.f;
                    val.y = v ? fmaxf(acc[fr][f][2 * s + 1] + sB1[ch + 1], 0.f) : 0.f;
                    *(float2*)(Hrow + ch) = val;
                    *(float2*)(Hcol + ch) = val;
                }
            }
        }
    }
}

// ---- Kernel 2: row conv  Q[b,u,i,j] = sum_{v,c} h[b,i,j+v-3,c] * W2[u,v,c] --
#define HSTR 36
__global__ __launch_bounds__(256) void k_rowconv(const float* __restrict__ W2,
                                                 const int* __restrict__ plen_p) {
    __shared__ __align__(16) float sH[262 * HSTR];   // 37.7 KB
    __shared__ __align__(16) float sW2[49 * CH];     // 6.3 KB
    const int tid = threadIdx.x;
    const int i = blockIdx.x, b = blockIdx.y;
    const int plen = __ldg(plen_p + b);
    const int j = tid;

    if (i >= plen) {                                 // h row exactly zero
        float* Qb = g_q + (size_t)b * 7 * (LQ * LQ) + (size_t)i * LQ + j;
        #pragma unroll
        for (int u = 0; u < 7; ++u) Qb[(size_t)u * (LQ * LQ)] = 0.f;
        return;
    }

    for (int t = tid; t < 49 * CH; t += 256) sW2[t] = W2[t];
    const float* Hrow = g_h + ((size_t)(b * LQ + i) * LQ) * CH;
    for (int idx = tid; idx < 262 * 8; idx += 256) {
        int p = idx >> 3, q = idx & 7;                 // pixel p = gj + 3
        int gj = p - 3;
        float4 v = (gj >= 0 && gj < LQ) ? ((const float4*)(Hrow + (size_t)gj * CH))[q]
                                        : make_float4(0.f, 0.f, 0.f, 0.f);
        *(float4*)(sH + p * HSTR + q * 4) = v;
    }
    __syncthreads();

    unsigned long long acc2[7][2];
    #pragma unroll
    for (int u = 0; u < 7; ++u) { acc2[u][0] = 0ull; acc2[u][1] = 0ull; }

    #pragma unroll
    for (int v = 0; v < 7; ++v) {
        const float* hp = sH + (j + v) * HSTR;
        unsigned long long h2[16];
        #pragma unroll
        for (int q = 0; q < 8; ++q) {
            float4 hv = *(const float4*)(hp + q * 4);
            h2[2*q] = pk2(hv.x, hv.y); h2[2*q+1] = pk2(hv.z, hv.w);
        }
        #pragma unroll
        for (int u = 0; u < 7; ++u) {
            const ulonglong2* wv = (const ulonglong2*)(sW2 + (u * 7 + v) * CH);
            #pragma unroll
            for (int k = 0; k < 8; ++k) {
                ulonglong2 wq = wv[k];
                fma2(acc2[u][0], h2[2*k],   wq.x);
                fma2(acc2[u][1], h2[2*k+1], wq.y);
            }
        }
    }
    float* Qb = g_q + (size_t)b * 7 * (LQ * LQ) + (size_t)i * LQ + j;
    #pragma unroll
    for (int u = 0; u < 7; ++u) {
        float2 fa = up2(acc2[u][0]), fb = up2(acc2[u][1]);
        Qb[(size_t)u * (LQ * LQ)] = (fa.x + fa.y) + (fb.x + fb.y);
    }
}

// ---- Kernel 3: col gather  out[b,i,j] = mask * (b2 + sum_u Q[b,u,i+u-3,j]) --
__global__ __launch_bounds__(256) void k_colgather(const int* __restrict__ plen_p,
                                                   const float* __restrict__ b2,
                                                   float* __restrict__ out) {
    const int j = threadIdx.x;
    const int i = blockIdx.x, b = blockIdx.y;
    const int plen = plen_p[b];
    const float* Qb = g_q + (size_t)b * 7 * (LQ * LQ) + j;
    float sum = 0.f;
    #pragma unroll
    for (int u = 0; u < 7; ++u) {
        int ii = i + u - 3;
        if (ii >= 0 && ii < LQ)
            sum += Qb[(size_t)u * (LQ * LQ) + (size_t)ii * LQ];
    }
    out[((size_t)b * LQ + i) * LQ + j] =
        (i < plen && j < plen) ? (sum + b2[0]) : 0.f;
}

extern "C" void kernel_launch(void* const* d_in, const int* in_sizes, int n_in,
                              void* d_out, int out_size) {
    const float* enc  = (const float*)d_in[0];
    const int*   plen = (const int*)d_in[1];
    const float* W1   = (const float*)d_in[2];
    const float* b1   = (const float*)d_in[3];
    const float* W2   = (const float*)d_in[4];
    const float* b2   = (const float*)d_in[5];
    float* out = (float*)d_out;

    k_prewf<<<64, 256>>>(W1);

    cudaFuncSetAttribute(k_pair, cudaFuncAttributeMaxDynamicSharedMemorySize, SMEM1);
    k_pair<<<NPERS, 256, SMEM1>>>(enc, plen, b1);   // persistent, work-stealing

    dim3 g2(LQ, BATCH);
    k_rowconv<<<g2, 256>>>(W2, plen);

    dim3 g3(LQ, BATCH);
    k_colgather<<<g3, 256>>>(plen, b2, out);
}

// round 16
// speedup vs baseline: 1.1839x; 1.1839x over previous
#include <cuda_runtime.h>
#include <cuda_fp16.h>
#include <cstdint>

#define LQ    256
#define DIM   256
#define CH    32
#define BATCH 8
#define XSTR  264   // floats; mod 32 == 8 -> conflict-free float2 LDS per 16-lane phase

// -------- scratch (device globals; no cudaMalloc allowed) -------------------
__device__ float g_h[(size_t)BATCH * LQ * LQ * CH];     // 64 MB hidden
__device__ float g_q[(size_t)BATCH * 7 * LQ * LQ];      // 14.7 MB row-conv
__device__ uint2 g_wh[4096];                            // W1 fp16 B-frags [h][db][f][lane]

#define NKEEP 144                         // upper-triangle 8x32 blocks per batch

// -------- f32x2 helpers (tail kernels) ---------------------------------------
__device__ __forceinline__ unsigned long long pk2(float lo, float hi) {
    unsigned long long r;
    asm("mov.b64 %0, {%1, %2};" : "=l"(r) : "f"(lo), "f"(hi));
    return r;
}
__device__ __forceinline__ void fma2(unsigned long long& a,
                                     unsigned long long x, unsigned long long y) {
    asm("fma.rn.f32x2 %0, %1, %2, %0;" : "+l"(a) : "l"(x), "l"(y));
}
__device__ __forceinline__ float2 up2(unsigned long long v) {
    float lo, hi;
    asm("mov.b64 {%0, %1}, %2;" : "=f"(lo), "=f"(hi) : "l"(v));
    return make_float2(lo, hi);
}

// -------- fp16 mma helpers ----------------------------------------------------
__device__ __forceinline__ uint32_t pkh2(float lo, float hi) {   // {lo, hi} f16x2
    __half2 h = __floats2half2_rn(lo, hi);
    return *(uint32_t*)&h;
}
__device__ __forceinline__ uint32_t habs2u(uint32_t v) {
    __half2 h = __habs2(*(__half2*)&v);
    return *(uint32_t*)&h;
}
__device__ __forceinline__ void mma_f16(float* d, const uint32_t* a, const uint32_t* b) {
    asm volatile(
        "mma.sync.aligned.m16n8k16.row.col.f32.f16.f16.f32 "
        "{%0,%1,%2,%3}, {%4,%5,%6,%7}, {%8,%9}, {%0,%1,%2,%3};"
        : "+f"(d[0]), "+f"(d[1]), "+f"(d[2]), "+f"(d[3])
        : "r"(a[0]), "r"(a[1]), "r"(a[2]), "r"(a[3]), "r"(b[0]), "r"(b[1]));
}

// ---- Kernel 0: precompute W1 fp16 B-fragments -------------------------------
// idx = ((h*16 + db)*4 + f)*32 + lane; b0 = (k=2tq,2tq+1), b1 = (k=2tq+8,+9),
// n = f*8 + tg, d = h*256 + db*16 + k.
__global__ __launch_bounds__(256) void k_prewf(const float* __restrict__ W1) {
    int idx = blockIdx.x * 256 + threadIdx.x;        // [0, 4096)
    int lane = idx & 31, f = (idx >> 5) & 3, db = (idx >> 7) & 15, h = idx >> 11;
    int tg = lane >> 2, tq = lane & 3;
    int n = f * 8 + tg;
    int dbase = h * 256 + db * 16;
    uint2 r;
    r.x = pkh2(W1[(dbase + 2 * tq)     * 32 + n], W1[(dbase + 2 * tq + 1) * 32 + n]);
    r.y = pkh2(W1[(dbase + 2 * tq + 8) * 32 + n], W1[(dbase + 2 * tq + 9) * 32 + n]);
    g_wh[idx] = r;
}

// smem layout for k_pair (byte offsets)
#define S_B1  0
#define S_XI  128
#define S_XJ  (S_XI + 8 * XSTR * 4)      // 8576
#define SMEM1 (S_XJ + 32 * XSTR * 4)     // 42368; 3 CTAs/SM = 127 KB < 228 KB

// ---- Kernel 1: symmetric pairwise-feature GEMM (mma.sync fp16, K=16) --------
// h[b,i,j,:] == h[b,j,i,:] exactly; compute only blocks with ib <= 4*jb+3 and
// mirror-write. Fully-masked tiles skip the MMA loop. CTA: 8 warps, 8i x 32j.
__global__ __launch_bounds__(256, 3)
void k_pair(const float* __restrict__ X, const int* __restrict__ plen_p,
            const float* __restrict__ b1) {
    extern __shared__ char smem[];
    float* sB1 = (float*)(smem + S_B1);
    float* sXi = (float*)(smem + S_XI);
    float* sXj = (float*)(smem + S_XJ);

    const int tid = threadIdx.x;
    const int w    = tid >> 5;
    const int lane = tid & 31;
    const int tg = lane >> 2, tq = lane & 3;
    const int b = blockIdx.z;

    // kept-block index -> (ib, jb): count up to jb is 2*jb^2+2*jb.
    const int idx = blockIdx.x;
    int jb = (int)floorf((sqrtf((float)(4 * idx) + 9.0f) - 3.0f) * 0.5f);
    while (2 * (jb + 1) * (jb + 1) + 2 * (jb + 1) <= idx) ++jb;
    while (2 * jb * jb + 2 * jb > idx) --jb;
    const int ib = idx - (2 * jb * jb + 2 * jb);
    const int i0 = ib * 8, j0 = jb * 32;
    const float* Xb = X + (size_t)b * LQ * DIM;
    const int plen = __ldg(plen_p + b);
    const bool live = (i0 < plen) && (j0 < plen);

    float acc[2][4][4];
    #pragma unroll
    for (int a = 0; a < 2; ++a)
        #pragma unroll
        for (int f = 0; f < 4; ++f)
            #pragma unroll
            for (int e = 0; e < 4; ++e) acc[a][f][e] = 0.f;

    if (tid < 32) sB1[tid] = b1[tid];

    if (live) {
        for (int t = tid; t < 8 * 64; t += 256) {
            int r = t >> 6, q = t & 63;
            *(float4*)(sXi + r * XSTR + q * 4) =
                ((const float4*)(Xb + (size_t)(i0 + r) * DIM))[q];
        }
        for (int t = tid; t < 32 * 64; t += 256) {
            int r = t >> 6, q = t & 63;
            *(float4*)(sXj + r * XSTR + q * 4) =
                ((const float4*)(Xb + (size_t)(j0 + r) * DIM))[q];
        }
        __syncthreads();

        const float* xiw = sXi + w * XSTR;

        #pragma unroll 2
        for (int db = 0; db < 16; ++db) {
            const int d0 = db * 16;
            // B fragments: mul half (h=0) and sub half (h=1)
            uint32_t Bm[4][2], Bs[4][2];
            #pragma unroll
            for (int f = 0; f < 4; ++f) {
                uint2 vm = __ldg(&g_wh[(db * 4 + f) * 32 + lane]);
                uint2 vs = __ldg(&g_wh[((16 + db) * 4 + f) * 32 + lane]);
                Bm[f][0] = vm.x; Bm[f][1] = vm.y;
                Bs[f][0] = vs.x; Bs[f][1] = vs.y;
            }
            // x data for this d-block (loaded ONCE, reused for mul and sub)
            float2 xiA = *(const float2*)(xiw + d0 + 2 * tq);        // broadcast
            float2 xiB = *(const float2*)(xiw + d0 + 2 * tq + 8);
            float2 xjA[4], xjB[4];                                   // rows tg+8r
            #pragma unroll
            for (int r = 0; r < 4; ++r) {
                const float* xr = sXj + (tg + r * 8) * XSTR + d0;
                xjA[r] = *(const float2*)(xr + 2 * tq);
                xjB[r] = *(const float2*)(xr + 2 * tq + 8);
            }
            uint32_t Am[2][4], As[2][4];
            #pragma unroll
            for (int fr = 0; fr < 2; ++fr) {
                const int r0 = 2 * fr, r1 = 2 * fr + 1;
                Am[fr][0] = pkh2(xiA.x * xjA[r0].x, xiA.y * xjA[r0].y);
                Am[fr][1] = pkh2(xiA.x * xjA[r1].x, xiA.y * xjA[r1].y);
                Am[fr][2] = pkh2(xiB.x * xjB[r0].x, xiB.y * xjB[r0].y);
                Am[fr][3] = pkh2(xiB.x * xjB[r1].x, xiB.y * xjB[r1].y);
                As[fr][0] = habs2u(pkh2(xiA.x - xjA[r0].x, xiA.y - xjA[r0].y));
                As[fr][1] = habs2u(pkh2(xiA.x - xjA[r1].x, xiA.y - xjA[r1].y));
                As[fr][2] = habs2u(pkh2(xiB.x - xjB[r0].x, xiB.y - xjB[r0].y));
                As[fr][3] = habs2u(pkh2(xiB.x - xjB[r1].x, xiB.y - xjB[r1].y));
            }
            #pragma unroll
            for (int fr = 0; fr < 2; ++fr)
                #pragma unroll
                for (int f = 0; f < 4; ++f) {
                    mma_f16(acc[fr][f], Am[fr], Bm[f]);
                    mma_f16(acc[fr][f], As[fr], Bs[f]);
                }
        }
    } else {
        __syncthreads();
    }

    // epilogue: bias + relu + mask -> g_h[b][i][j][:] AND mirror g_h[b][j][i][:]
    const int gi = i0 + w;
    const bool vi = gi < plen;
    #pragma unroll
    for (int fr = 0; fr < 2; ++fr) {
        #pragma unroll
        for (int s = 0; s < 2; ++s) {
            const int gj = j0 + fr * 16 + tg + 8 * s;
            const bool v = vi && (gj < plen);
            float* Hrow = g_h + ((size_t)(b * LQ + gi) * LQ + gj) * CH;
            float* Hcol = g_h + ((size_t)(b * LQ + gj) * LQ + gi) * CH;
            #pragma unroll
            for (int f = 0; f < 4; ++f) {
                const int ch = f * 8 + 2 * tq;
                float2 val;
                val.x = v ? fmaxf(acc[fr][f][2 * s]     + sB1[ch],     0.f) : 0.f;
                val.y = v ? fmaxf(acc[fr][f][2 * s + 1] + sB1[ch + 1], 0.f) : 0.f;
                *(float2*)(Hrow + ch) = val;
                *(float2*)(Hcol + ch) = val;
            }
        }
    }
}

// ---- Kernel 2: row conv  Q[b,u,i,j] = sum_{v,c} h[b,i,j+v-3,c] * W2[u,v,c] --
#define HSTR 36
__global__ __launch_bounds__(256) void k_rowconv(const float* __restrict__ W2,
                                                 const int* __restrict__ plen_p) {
    __shared__ __align__(16) float sH[262 * HSTR];   // 37.7 KB
    __shared__ __align__(16) float sW2[49 * CH];     // 6.3 KB
    const int tid = threadIdx.x;
    const int i = blockIdx.x, b = blockIdx.y;
    const int plen = __ldg(plen_p + b);
    const int j = tid;

    if (i >= plen) {                                 // h row exactly zero
        float* Qb = g_q + (size_t)b * 7 * (LQ * LQ) + (size_t)i * LQ + j;
        #pragma unroll
        for (int u = 0; u < 7; ++u) Qb[(size_t)u * (LQ * LQ)] = 0.f;
        return;
    }

    for (int t = tid; t < 49 * CH; t += 256) sW2[t] = W2[t];
    const float* Hrow = g_h + ((size_t)(b * LQ + i) * LQ) * CH;
    for (int idx = tid; idx < 262 * 8; idx += 256) {
        int p = idx >> 3, q = idx & 7;                 // pixel p = gj + 3
        int gj = p - 3;
        float4 v = (gj >= 0 && gj < LQ) ? ((const float4*)(Hrow + (size_t)gj * CH))[q]
                                        : make_float4(0.f, 0.f, 0.f, 0.f);
        *(float4*)(sH + p * HSTR + q * 4) = v;
    }
    __syncthreads();

    unsigned long long acc2[7][2];
    #pragma unroll
    for (int u = 0; u < 7; ++u) { acc2[u][0] = 0ull; acc2[u][1] = 0ull; }

    #pragma unroll
    for (int v = 0; v < 7; ++v) {
        const float* hp = sH + (j + v) * HSTR;
        unsigned long long h2[16];
        #pragma unroll
        for (int q = 0; q < 8; ++q) {
            float4 hv = *(const float4*)(hp + q * 4);
            h2[2*q] = pk2(hv.x, hv.y); h2[2*q+1] = pk2(hv.z, hv.w);
        }
        #pragma unroll
        for (int u = 0; u < 7; ++u) {
            const ulonglong2* wv = (const ulonglong2*)(sW2 + (u * 7 + v) * CH);
            #pragma unroll
            for (int k = 0; k < 8; ++k) {
                ulonglong2 wq = wv[k];
                fma2(acc2[u][0], h2[2*k],   wq.x);
                fma2(acc2[u][1], h2[2*k+1], wq.y);
            }
        }
    }
    float* Qb = g_q + (size_t)b * 7 * (LQ * LQ) + (size_t)i * LQ + j;
    #pragma unroll
    for (int u = 0; u < 7; ++u) {
        float2 fa = up2(acc2[u][0]), fb = up2(acc2[u][1]);
        Qb[(size_t)u * (LQ * LQ)] = (fa.x + fa.y) + (fb.x + fb.y);
    }
}

// ---- Kernel 3: col gather  out[b,i,j] = mask * (b2 + sum_u Q[b,u,i+u-3,j]) --
__global__ __launch_bounds__(256) void k_colgather(const int* __restrict__ plen_p,
                                                   const float* __restrict__ b2,
                                                   float* __restrict__ out) {
    const int j = threadIdx.x;
    const int i = blockIdx.x, b = blockIdx.y;
    const int plen = plen_p[b];
    const float* Qb = g_q + (size_t)b * 7 * (LQ * LQ) + j;
    float sum = 0.f;
    #pragma unroll
    for (int u = 0; u < 7; ++u) {
        int ii = i + u - 3;
        if (ii >= 0 && ii < LQ)
            sum += Qb[(size_t)u * (LQ * LQ) + (size_t)ii * LQ];
    }
    out[((size_t)b * LQ + i) * LQ + j] =
        (i < plen && j < plen) ? (sum + b2[0]) : 0.f;
}

extern "C" void kernel_launch(void* const* d_in, const int* in_sizes, int n_in,
                              void* d_out, int out_size) {
    const float* enc  = (const float*)d_in[0];
    const int*   plen = (const int*)d_in[1];
    const float* W1   = (const float*)d_in[2];
    const float* b1   = (const float*)d_in[3];
    const float* W2   = (const float*)d_in[4];
    const float* b2   = (const float*)d_in[5];
    float* out = (float*)d_out;

    k_prewf<<<16, 256>>>(W1);

    cudaFuncSetAttribute(k_pair, cudaFuncAttributeMaxDynamicSharedMemorySize, SMEM1);
    dim3 g1(NKEEP, 1, BATCH);                   // 144 upper-tri blocks x 8 batches
    k_pair<<<g1, 256, SMEM1>>>(enc, plen, b1);

    dim3 g2(LQ, BATCH);
    k_rowconv<<<g2, 256>>>(W2, plen);

    dim3 g3(LQ, BATCH);
    k_colgather<<<g3, 256>>>(plen, b2, out);
}